// round 11
// baseline (speedup 1.0000x reference)
#include <cuda_runtime.h>
#include <math.h>

#define B_    16
#define CIN   128
#define COUT  256
#define HW    56
#define HWHW  3136
#define TILES 784            /* 28x28 per image, 2x2 outputs */
#define MW    12544          /* 16*784 tiles (GEMM M) */
#define KW    256            /* 2*CIN cos/sin (GEMM K) */
#define NW    256            /* couts, f32x2-packed (GEMM N) */
#define NXI   16             /* 4x4 Winograd positions */

#define BM 64
#define BN 128
#define BK 16
#define NKT (KW/BK)          /* 16 */
#define GTH 128

#define AS_STG (BK*BM)                   /* u64 per A stage: 1024 (8KB) */
#define BS_STG (BK*BN)                   /* u64 per B stage: 2048 (16KB) */
#define SMEM_DYN (3*(AS_STG+BS_STG)*8)   /* 73728 B */

typedef unsigned long long u64;

/* device scratch (zero-init) */
static __device__ float2 g_cs[(size_t)B_ * CIN * HWHW];        /*  51 MB */
static __device__ u64    g_V[(size_t)NXI * KW * MW];           /* 411 MB (pre-broadcast) */
static __device__ u64    g_U[(size_t)NXI * KW * NW];           /* 8.4 MB */
static __device__ u64    g_M[(size_t)NXI * NW * MW];           /* 411 MB */

__device__ __forceinline__ void fma2(u64& acc, u64 a, u64 b) {
    asm("fma.rn.f32x2 %0, %1, %2, %0;" : "+l"(acc) : "l"(a), "l"(b));
}
__device__ __forceinline__ u64 add2(u64 a, u64 b) {
    u64 r; asm("add.rn.f32x2 %0, %1, %2;" : "=l"(r) : "l"(a), "l"(b)); return r;
}
__device__ __forceinline__ u64 sub2(u64 a, u64 b) {
    u64 r; asm("sub.rn.f32x2 %0, %1, %2;" : "=l"(r) : "l"(a), "l"(b)); return r;
}
__device__ __forceinline__ u64 bcast2(float v) {
    u64 r; asm("mov.b64 %0, {%1, %1};" : "=l"(r) : "f"(v)); return r;
}
__device__ __forceinline__ u64 pack2(float lo, float hi) {
    u64 r; asm("mov.b64 %0, {%1, %2};" : "=l"(r) : "f"(lo), "f"(hi)); return r;
}
__device__ __forceinline__ void unpack2(u64 v, float& lo, float& hi) {
    asm("mov.b64 {%0, %1}, %2;" : "=f"(lo), "=f"(hi) : "l"(v));
}
__device__ __forceinline__ void cpa16(void* dst, const void* src) {
    unsigned d = (unsigned)__cvta_generic_to_shared(dst);
    asm volatile("cp.async.cg.shared.global [%0], [%1], 16;" :: "r"(d), "l"(src) : "memory");
}

/* ---------- prep: sincos of x ---------- */
__global__ void prep_input_kernel(const float* __restrict__ x) {
    int idx = blockIdx.x * blockDim.x + threadIdx.x;
    if (idx >= B_ * CIN * HWHW) return;
    float s, c;
    sincosf(x[idx], &s, &c);
    g_cs[idx] = make_float2(c, s);
}

/* ---------- F(2,3) weight transform: U = G g G^T, packed (re,im) ---------- */
__global__ void wino_wprep(const float* __restrict__ probe,
                           const float* __restrict__ oang) {
    int idx = blockIdx.x * blockDim.x + threadIdx.x;   /* 256*256 */
    int co = idx & 255;
    int c  = idx >> 8;             /* cin2: 2*ci + s */
    int ci = c >> 1, s = c & 1;
    float gre[3][3], gim[3][3];
#pragma unroll
    for (int tap = 0; tap < 9; tap++) {
        int pidx = ci * 2304 + co * 9 + tap;
        float p = probe[pidx], o = oang[pidx];
        float sp, cp, so, c_o;
        sincosf(p, &sp, &cp);
        sincosf(o, &so, &c_o);
        float a = s ? sp : cp;
        gre[tap / 3][tap % 3] = a * c_o;
        gim[tap / 3][tap % 3] = a * so;
    }
    float Ur[4][4], Ui[4][4];
    {
        float t[4][3];
#pragma unroll
        for (int j = 0; j < 3; j++) {
            t[0][j] = gre[0][j];
            t[1][j] = 0.5f * (gre[0][j] + gre[1][j] + gre[2][j]);
            t[2][j] = 0.5f * (gre[0][j] - gre[1][j] + gre[2][j]);
            t[3][j] = gre[2][j];
        }
#pragma unroll
        for (int i = 0; i < 4; i++) {
            Ur[i][0] = t[i][0];
            Ur[i][1] = 0.5f * (t[i][0] + t[i][1] + t[i][2]);
            Ur[i][2] = 0.5f * (t[i][0] - t[i][1] + t[i][2]);
            Ur[i][3] = t[i][2];
        }
    }
    {
        float t[4][3];
#pragma unroll
        for (int j = 0; j < 3; j++) {
            t[0][j] = gim[0][j];
            t[1][j] = 0.5f * (gim[0][j] + gim[1][j] + gim[2][j]);
            t[2][j] = 0.5f * (gim[0][j] - gim[1][j] + gim[2][j]);
            t[3][j] = gim[2][j];
        }
#pragma unroll
        for (int i = 0; i < 4; i++) {
            Ui[i][0] = t[i][0];
            Ui[i][1] = 0.5f * (t[i][0] + t[i][1] + t[i][2]);
            Ui[i][2] = 0.5f * (t[i][0] - t[i][1] + t[i][2]);
            Ui[i][3] = t[i][2];
        }
    }
#pragma unroll
    for (int i = 0; i < 4; i++)
#pragma unroll
        for (int j = 0; j < 4; j++)
            g_U[(size_t)(i * 4 + j) * KW * NW + (size_t)c * NW + co] =
                pack2(Ur[i][j], Ui[i][j]);
}

/* ---------- F(2,3) input transform: V = B^T d B, stored broadcast (v,v) ---------- */
__global__ void wino_vprep() {
    int m  = blockIdx.x * 256 + threadIdx.x;   /* grid.x = 49 */
    int ci = blockIdx.y;                       /* 0..127 */
    int b  = m / TILES;
    int t  = m - b * TILES;
    int ty = t / 28, tx = t - (t / 28) * 28;
    const float2* plane = g_cs + ((size_t)b * CIN + ci) * HWHW;
    float dc[4][4], ds[4][4];
#pragma unroll
    for (int i = 0; i < 4; i++) {
        int r = 2 * ty - 1 + i;
#pragma unroll
        for (int j = 0; j < 4; j++) {
            int cc = 2 * tx - 1 + j;
            float2 v = make_float2(0.f, 0.f);
            if ((unsigned)r < HW && (unsigned)cc < HW) v = plane[r * HW + cc];
            dc[i][j] = v.x; ds[i][j] = v.y;
        }
    }
    float Vc[4][4], Vs[4][4];
    {
        float tt[4][4];
#pragma unroll
        for (int j = 0; j < 4; j++) {
            tt[0][j] = dc[0][j] - dc[2][j];
            tt[1][j] = dc[1][j] + dc[2][j];
            tt[2][j] = dc[2][j] - dc[1][j];
            tt[3][j] = dc[1][j] - dc[3][j];
        }
#pragma unroll
        for (int i = 0; i < 4; i++) {
            Vc[i][0] = tt[i][0] - tt[i][2];
            Vc[i][1] = tt[i][1] + tt[i][2];
            Vc[i][2] = tt[i][2] - tt[i][1];
            Vc[i][3] = tt[i][1] - tt[i][3];
        }
    }
    {
        float tt[4][4];
#pragma unroll
        for (int j = 0; j < 4; j++) {
            tt[0][j] = ds[0][j] - ds[2][j];
            tt[1][j] = ds[1][j] + ds[2][j];
            tt[2][j] = ds[2][j] - ds[1][j];
            tt[3][j] = ds[1][j] - ds[3][j];
        }
#pragma unroll
        for (int i = 0; i < 4; i++) {
            Vs[i][0] = tt[i][0] - tt[i][2];
            Vs[i][1] = tt[i][1] + tt[i][2];
            Vs[i][2] = tt[i][2] - tt[i][1];
            Vs[i][3] = tt[i][1] - tt[i][3];
        }
    }
#pragma unroll
    for (int i = 0; i < 4; i++)
#pragma unroll
        for (int j = 0; j < 4; j++) {
            u64* base = g_V + (size_t)(i * 4 + j) * KW * MW;
            base[(size_t)(2 * ci)     * MW + m] = bcast2(Vc[i][j]);
            base[(size_t)(2 * ci + 1) * MW + m] = bcast2(Vs[i][j]);
        }
}

/* ---------- batched GEMM: M_xi = V_xi^T x U_xi, 8x8 f32x2 tiles ---------- */
__global__ __launch_bounds__(GTH, 1) void wino_gemm() {
    extern __shared__ __align__(16) char smraw[];
    u64* As = (u64*)smraw;                        /* [3][BK][BM] */
    u64* Bs = (u64*)(smraw + 3 * AS_STG * 8);     /* [3][BK][BN] */
    const int tid = threadIdx.x;
    const int mb = blockIdx.x * BM;
    const int nb = blockIdx.y * BN;
    const int xi = blockIdx.z;
    const u64* Ap = g_V + (size_t)xi * KW * MW;
    const u64* Bp = g_U + (size_t)xi * KW * NW;
    const int m0 = (tid & 7) * 8;
    const int n0 = (tid >> 3) * 8;

    u64 acc[8][8];
#pragma unroll
    for (int i = 0; i < 8; i++)
#pragma unroll
        for (int j = 0; j < 8; j++) acc[i][j] = 0ULL;

    auto load_stage = [&](int kt, int s) {
#pragma unroll
        for (int u = 0; u < 4; u++) {            /* A: 512 x 16B */
            int ch = u * GTH + tid;
            int r = ch >> 5, col = (ch & 31) * 2;
            cpa16(As + s * AS_STG + r * BM + col,
                  Ap + (size_t)(kt * BK + r) * MW + mb + col);
        }
#pragma unroll
        for (int u = 0; u < 8; u++) {            /* B: 1024 x 16B */
            int ch = u * GTH + tid;
            int r = ch >> 6, col = (ch & 63) * 2;
            cpa16(Bs + s * BS_STG + r * BN + col,
                  Bp + (size_t)(kt * BK + r) * NW + nb + col);
        }
    };

    load_stage(0, 0);
    asm volatile("cp.async.commit_group;" ::: "memory");
    load_stage(1, 1);
    asm volatile("cp.async.commit_group;" ::: "memory");

#pragma unroll 1
    for (int kt = 0; kt < NKT; kt++) {
        if (kt + 2 < NKT) load_stage(kt + 2, (kt + 2) % 3);
        asm volatile("cp.async.commit_group;" ::: "memory");
        asm volatile("cp.async.wait_group 2;" ::: "memory");
        __syncthreads();
        const int s = kt % 3;
        const u64* Ab = As + s * AS_STG + m0;
        const u64* Bb = Bs + s * BS_STG + n0;
#pragma unroll
        for (int kk = 0; kk < BK; kk++) {
            u64 a[8], b[8];
#pragma unroll
            for (int q = 0; q < 4; q++)
                *(float4*)&a[q * 2] = *(const float4*)&Ab[kk * BM + q * 2];
#pragma unroll
            for (int q = 0; q < 4; q++)
                *(float4*)&b[q * 2] = *(const float4*)&Bb[kk * BN + q * 2];
#pragma unroll
            for (int i = 0; i < 8; i++)
#pragma unroll
                for (int j = 0; j < 8; j++)
                    fma2(acc[i][j], a[i], b[j]);
        }
        __syncthreads();
    }

    u64* Mp = g_M + (size_t)xi * NW * MW;
#pragma unroll
    for (int j = 0; j < 8; j++) {
        u64* row = Mp + (size_t)(nb + n0 + j) * MW + mb + m0;
#pragma unroll
        for (int i = 0; i < 8; i++) row[i] = acc[i][j];
    }
}

/* ---------- output transform: Y = A^T M A (packed), atan2, store ---------- */
__global__ void wino_out(float* __restrict__ out) {
    int m = blockIdx.x * 256 + threadIdx.x;    /* grid.x = 49 */
    int n = blockIdx.y;                        /* cout 0..255 */
    u64 Mv[4][4];
#pragma unroll
    for (int i = 0; i < 4; i++)
#pragma unroll
        for (int j = 0; j < 4; j++)
            Mv[i][j] = g_M[(size_t)(i * 4 + j) * NW * MW + (size_t)n * MW + m];

    u64 t0[4], t1[4];
#pragma unroll
    for (int j = 0; j < 4; j++) {
        t0[j] = add2(add2(Mv[0][j], Mv[1][j]), Mv[2][j]);
        t1[j] = sub2(sub2(Mv[1][j], Mv[2][j]), Mv[3][j]);
    }
    u64 y00 = add2(add2(t0[0], t0[1]), t0[2]);
    u64 y01 = sub2(sub2(t0[1], t0[2]), t0[3]);
    u64 y10 = add2(add2(t1[0], t1[1]), t1[2]);
    u64 y11 = sub2(sub2(t1[1], t1[2]), t1[3]);

    int b  = m / TILES;
    int t  = m - b * TILES;
    int ty = t / 28, tx = t - (t / 28) * 28;
    float* ob = out + ((size_t)b * COUT + n) * HWHW + (2 * ty) * HW + 2 * tx;
    float re, im;
    unpack2(y00, re, im); ob[0]      = atan2f(im, re);
    unpack2(y01, re, im); ob[1]      = atan2f(im, re);
    unpack2(y10, re, im); ob[HW]     = atan2f(im, re);
    unpack2(y11, re, im); ob[HW + 1] = atan2f(im, re);
}

/* ---------- launch ---------- */
extern "C" void kernel_launch(void* const* d_in, const int* in_sizes, int n_in,
                              void* d_out, int out_size) {
    const float* x     = (const float*)d_in[0];
    const float* probe = (const float*)d_in[1];
    const float* oang  = (const float*)d_in[2];
    float* out = (float*)d_out;

    cudaFuncSetAttribute(wino_gemm, cudaFuncAttributeMaxDynamicSharedMemorySize, SMEM_DYN);

    prep_input_kernel<<<(B_ * CIN * HWHW + 255) / 256, 256>>>(x);
    wino_wprep<<<(KW * NW) / 256, 256>>>(probe, oang);
    {
        dim3 g(MW / 256, CIN);
        wino_vprep<<<g, 256>>>();
    }
    {
        dim3 g(MW / BM, NW / BN, NXI);         /* (196, 2, 16) */
        wino_gemm<<<g, GTH, SMEM_DYN>>>();
    }
    {
        dim3 g(MW / 256, NW);
        wino_out<<<g, 256>>>(out);
    }
}

// round 12
// speedup vs baseline: 1.4526x; 1.4526x over previous
#include <cuda_runtime.h>
#include <math.h>

#define B_    16
#define CIN   128
#define COUT  256
#define HW    56
#define HWHW  3136
#define TILES 784            /* 28x28 per image, 2x2 outputs */
#define MW    12544          /* 16*784 tiles (GEMM M) */
#define KW    256            /* 2*CIN cos/sin (GEMM K) */
#define NW    256            /* couts, f32x2-packed (GEMM N) */
#define NXI   16             /* 4x4 Winograd positions */

#define BM 64
#define BN 64
#define BK 16
#define NKT (KW/BK)          /* 16 */
#define GTH 128

#define AS_STG (BK*BM)                    /* u64 per A stage: 1024 (8KB) */
#define BS_STG (BK*BN)                    /* u64 per B stage: 1024 (8KB) */
#define SMEM_DYN (3*(AS_STG+BS_STG)*8)    /* 49152 B */

typedef unsigned long long u64;

/* device scratch (zero-init) */
static __device__ float2 g_cs[(size_t)B_ * CIN * HWHW];        /*  51 MB */
static __device__ u64    g_V[(size_t)NXI * KW * MW];           /* 411 MB (pre-broadcast) */
static __device__ u64    g_U[(size_t)NXI * KW * NW];           /* 8.4 MB */
static __device__ u64    g_M[(size_t)NXI * NW * MW];           /* 411 MB */

__device__ __forceinline__ void fma2(u64& acc, u64 a, u64 b) {
    asm("fma.rn.f32x2 %0, %1, %2, %0;" : "+l"(acc) : "l"(a), "l"(b));
}
__device__ __forceinline__ u64 add2(u64 a, u64 b) {
    u64 r; asm("add.rn.f32x2 %0, %1, %2;" : "=l"(r) : "l"(a), "l"(b)); return r;
}
__device__ __forceinline__ u64 sub2(u64 a, u64 b) {
    u64 r; asm("sub.rn.f32x2 %0, %1, %2;" : "=l"(r) : "l"(a), "l"(b)); return r;
}
__device__ __forceinline__ u64 bcast2(float v) {
    u64 r; asm("mov.b64 %0, {%1, %1};" : "=l"(r) : "f"(v)); return r;
}
__device__ __forceinline__ u64 pack2(float lo, float hi) {
    u64 r; asm("mov.b64 %0, {%1, %2};" : "=l"(r) : "f"(lo), "f"(hi)); return r;
}
__device__ __forceinline__ void unpack2(u64 v, float& lo, float& hi) {
    asm("mov.b64 {%0, %1}, %2;" : "=f"(lo), "=f"(hi) : "l"(v));
}
__device__ __forceinline__ void cpa16(void* dst, const void* src) {
    unsigned d = (unsigned)__cvta_generic_to_shared(dst);
    asm volatile("cp.async.cg.shared.global [%0], [%1], 16;" :: "r"(d), "l"(src) : "memory");
}

/* ---------- prep: sincos of x ---------- */
__global__ void prep_input_kernel(const float* __restrict__ x) {
    int idx = blockIdx.x * blockDim.x + threadIdx.x;
    if (idx >= B_ * CIN * HWHW) return;
    float s, c;
    sincosf(x[idx], &s, &c);
    g_cs[idx] = make_float2(c, s);
}

/* ---------- F(2,3) weight transform: U = G g G^T, packed (re,im) ---------- */
__global__ void wino_wprep(const float* __restrict__ probe,
                           const float* __restrict__ oang) {
    int idx = blockIdx.x * blockDim.x + threadIdx.x;   /* 256*256 */
    int co = idx & 255;
    int c  = idx >> 8;             /* cin2: 2*ci + s */
    int ci = c >> 1, s = c & 1;
    float gre[3][3], gim[3][3];
#pragma unroll
    for (int tap = 0; tap < 9; tap++) {
        int pidx = ci * 2304 + co * 9 + tap;
        float p = probe[pidx], o = oang[pidx];
        float sp, cp, so, c_o;
        sincosf(p, &sp, &cp);
        sincosf(o, &so, &c_o);
        float a = s ? sp : cp;
        gre[tap / 3][tap % 3] = a * c_o;
        gim[tap / 3][tap % 3] = a * so;
    }
    float Ur[4][4], Ui[4][4];
    {
        float t[4][3];
#pragma unroll
        for (int j = 0; j < 3; j++) {
            t[0][j] = gre[0][j];
            t[1][j] = 0.5f * (gre[0][j] + gre[1][j] + gre[2][j]);
            t[2][j] = 0.5f * (gre[0][j] - gre[1][j] + gre[2][j]);
            t[3][j] = gre[2][j];
        }
#pragma unroll
        for (int i = 0; i < 4; i++) {
            Ur[i][0] = t[i][0];
            Ur[i][1] = 0.5f * (t[i][0] + t[i][1] + t[i][2]);
            Ur[i][2] = 0.5f * (t[i][0] - t[i][1] + t[i][2]);
            Ur[i][3] = t[i][2];
        }
    }
    {
        float t[4][3];
#pragma unroll
        for (int j = 0; j < 3; j++) {
            t[0][j] = gim[0][j];
            t[1][j] = 0.5f * (gim[0][j] + gim[1][j] + gim[2][j]);
            t[2][j] = 0.5f * (gim[0][j] - gim[1][j] + gim[2][j]);
            t[3][j] = gim[2][j];
        }
#pragma unroll
        for (int i = 0; i < 4; i++) {
            Ui[i][0] = t[i][0];
            Ui[i][1] = 0.5f * (t[i][0] + t[i][1] + t[i][2]);
            Ui[i][2] = 0.5f * (t[i][0] - t[i][1] + t[i][2]);
            Ui[i][3] = t[i][2];
        }
    }
#pragma unroll
    for (int i = 0; i < 4; i++)
#pragma unroll
        for (int j = 0; j < 4; j++)
            g_U[(size_t)(i * 4 + j) * KW * NW + (size_t)c * NW + co] =
                pack2(Ur[i][j], Ui[i][j]);
}

/* ---------- F(2,3) input transform: V = B^T d B, stored broadcast (v,v) ---------- */
__global__ void wino_vprep() {
    int m  = blockIdx.x * 256 + threadIdx.x;   /* grid.x = 49 */
    int ci = blockIdx.y;                       /* 0..127 */
    int b  = m / TILES;
    int t  = m - b * TILES;
    int ty = t / 28, tx = t - (t / 28) * 28;
    const float2* plane = g_cs + ((size_t)b * CIN + ci) * HWHW;
    float dc[4][4], ds[4][4];
#pragma unroll
    for (int i = 0; i < 4; i++) {
        int r = 2 * ty - 1 + i;
#pragma unroll
        for (int j = 0; j < 4; j++) {
            int cc = 2 * tx - 1 + j;
            float2 v = make_float2(0.f, 0.f);
            if ((unsigned)r < HW && (unsigned)cc < HW) v = plane[r * HW + cc];
            dc[i][j] = v.x; ds[i][j] = v.y;
        }
    }
    float Vc[4][4], Vs[4][4];
    {
        float tt[4][4];
#pragma unroll
        for (int j = 0; j < 4; j++) {
            tt[0][j] = dc[0][j] - dc[2][j];
            tt[1][j] = dc[1][j] + dc[2][j];
            tt[2][j] = dc[2][j] - dc[1][j];
            tt[3][j] = dc[1][j] - dc[3][j];
        }
#pragma unroll
        for (int i = 0; i < 4; i++) {
            Vc[i][0] = tt[i][0] - tt[i][2];
            Vc[i][1] = tt[i][1] + tt[i][2];
            Vc[i][2] = tt[i][2] - tt[i][1];
            Vc[i][3] = tt[i][1] - tt[i][3];
        }
    }
    {
        float tt[4][4];
#pragma unroll
        for (int j = 0; j < 4; j++) {
            tt[0][j] = ds[0][j] - ds[2][j];
            tt[1][j] = ds[1][j] + ds[2][j];
            tt[2][j] = ds[2][j] - ds[1][j];
            tt[3][j] = ds[1][j] - ds[3][j];
        }
#pragma unroll
        for (int i = 0; i < 4; i++) {
            Vs[i][0] = tt[i][0] - tt[i][2];
            Vs[i][1] = tt[i][1] + tt[i][2];
            Vs[i][2] = tt[i][2] - tt[i][1];
            Vs[i][3] = tt[i][1] - tt[i][3];
        }
    }
#pragma unroll
    for (int i = 0; i < 4; i++)
#pragma unroll
        for (int j = 0; j < 4; j++) {
            u64* base = g_V + (size_t)(i * 4 + j) * KW * MW;
            base[(size_t)(2 * ci)     * MW + m] = bcast2(Vc[i][j]);
            base[(size_t)(2 * ci + 1) * MW + m] = bcast2(Vs[i][j]);
        }
}

/* ---------- batched GEMM: M_xi = V_xi^T x U_xi, 4m x 8n f32x2 tiles ---------- */
__global__ __launch_bounds__(GTH) void wino_gemm() {
    extern __shared__ __align__(16) char smraw[];
    u64* As = (u64*)smraw;                        /* [3][BK][BM] */
    u64* Bs = (u64*)(smraw + 3 * AS_STG * 8);     /* [3][BK][BN] */
    const int tid = threadIdx.x;
    const int mb = blockIdx.x * BM;
    const int nb = blockIdx.y * BN;
    const int xi = blockIdx.z;
    const u64* Ap = g_V + (size_t)xi * KW * MW;
    const u64* Bp = g_U + (size_t)xi * KW * NW;
    const int m0 = (tid & 15) * 4;
    const int n0 = (tid >> 4) * 8;

    u64 acc[4][8];
#pragma unroll
    for (int i = 0; i < 4; i++)
#pragma unroll
        for (int j = 0; j < 8; j++) acc[i][j] = 0ULL;

    auto load_stage = [&](int kt, int s) {
#pragma unroll
        for (int u = 0; u < 4; u++) {            /* A: 512 x 16B */
            int ch = u * GTH + tid;
            int r = ch >> 5, col = (ch & 31) * 2;
            cpa16(As + s * AS_STG + r * BM + col,
                  Ap + (size_t)(kt * BK + r) * MW + mb + col);
        }
#pragma unroll
        for (int u = 0; u < 4; u++) {            /* B: 512 x 16B */
            int ch = u * GTH + tid;
            int r = ch >> 5, col = (ch & 31) * 2;
            cpa16(Bs + s * BS_STG + r * BN + col,
                  Bp + (size_t)(kt * BK + r) * NW + nb + col);
        }
    };

    load_stage(0, 0);
    asm volatile("cp.async.commit_group;" ::: "memory");
    load_stage(1, 1);
    asm volatile("cp.async.commit_group;" ::: "memory");

#pragma unroll 1
    for (int kt = 0; kt < NKT; kt++) {
        if (kt + 2 < NKT) load_stage(kt + 2, (kt + 2) % 3);
        asm volatile("cp.async.commit_group;" ::: "memory");
        asm volatile("cp.async.wait_group 2;" ::: "memory");
        __syncthreads();
        const int s = kt % 3;
        const u64* Ab = As + s * AS_STG + m0;
        const u64* Bb = Bs + s * BS_STG + n0;
#pragma unroll
        for (int kk = 0; kk < BK; kk++) {
            u64 a[4], b[8];
            *(float4*)&a[0] = *(const float4*)&Ab[kk * BM];
            *(float4*)&a[2] = *(const float4*)&Ab[kk * BM + 2];
#pragma unroll
            for (int q = 0; q < 4; q++)
                *(float4*)&b[q * 2] = *(const float4*)&Bb[kk * BN + q * 2];
#pragma unroll
            for (int i = 0; i < 4; i++)
#pragma unroll
                for (int j = 0; j < 8; j++)
                    fma2(acc[i][j], a[i], b[j]);
        }
        __syncthreads();
    }

    u64* Mp = g_M + (size_t)xi * NW * MW;
#pragma unroll
    for (int j = 0; j < 8; j++) {
        u64* row = Mp + (size_t)(nb + n0 + j) * MW + mb + m0;
#pragma unroll
        for (int i = 0; i < 4; i++) row[i] = acc[i][j];
    }
}

/* ---------- output transform: Y = A^T M A (packed), atan2, store ---------- */
__global__ void wino_out(float* __restrict__ out) {
    int m = blockIdx.x * 256 + threadIdx.x;    /* grid.x = 49 */
    int n = blockIdx.y;                        /* cout 0..255 */
    u64 Mv[4][4];
#pragma unroll
    for (int i = 0; i < 4; i++)
#pragma unroll
        for (int j = 0; j < 4; j++)
            Mv[i][j] = g_M[(size_t)(i * 4 + j) * NW * MW + (size_t)n * MW + m];

    u64 t0[4], t1[4];
#pragma unroll
    for (int j = 0; j < 4; j++) {
        t0[j] = add2(add2(Mv[0][j], Mv[1][j]), Mv[2][j]);
        t1[j] = sub2(sub2(Mv[1][j], Mv[2][j]), Mv[3][j]);
    }
    u64 y00 = add2(add2(t0[0], t0[1]), t0[2]);
    u64 y01 = sub2(sub2(t0[1], t0[2]), t0[3]);
    u64 y10 = add2(add2(t1[0], t1[1]), t1[2]);
    u64 y11 = sub2(sub2(t1[1], t1[2]), t1[3]);

    int b  = m / TILES;
    int t  = m - b * TILES;
    int ty = t / 28, tx = t - (t / 28) * 28;
    float* ob = out + ((size_t)b * COUT + n) * HWHW + (2 * ty) * HW + 2 * tx;
    float re, im;
    unpack2(y00, re, im); ob[0]      = atan2f(im, re);
    unpack2(y01, re, im); ob[1]      = atan2f(im, re);
    unpack2(y10, re, im); ob[HW]     = atan2f(im, re);
    unpack2(y11, re, im); ob[HW + 1] = atan2f(im, re);
}

/* ---------- launch ---------- */
extern "C" void kernel_launch(void* const* d_in, const int* in_sizes, int n_in,
                              void* d_out, int out_size) {
    const float* x     = (const float*)d_in[0];
    const float* probe = (const float*)d_in[1];
    const float* oang  = (const float*)d_in[2];
    float* out = (float*)d_out;

    cudaFuncSetAttribute(wino_gemm, cudaFuncAttributeMaxDynamicSharedMemorySize, SMEM_DYN);

    prep_input_kernel<<<(B_ * CIN * HWHW + 255) / 256, 256>>>(x);
    wino_wprep<<<(KW * NW) / 256, 256>>>(probe, oang);
    {
        dim3 g(MW / 256, CIN);
        wino_vprep<<<g, 256>>>();
    }
    {
        dim3 g(MW / BM, NW / BN, NXI);         /* (196, 4, 16) */
        wino_gemm<<<g, GTH, SMEM_DYN>>>();
    }
    {
        dim3 g(MW / 256, NW);
        wino_out<<<g, 256>>>(out);
    }
}

// round 14
// speedup vs baseline: 1.8988x; 1.3072x over previous
#include <cuda_runtime.h>
#include <math.h>

#define B_    16
#define CIN   128
#define COUT  256
#define HW    56
#define HWHW  3136
#define TILES 784            /* 28x28 per image, 2x2 outputs */
#define MW    12544          /* 16*784 tiles (GEMM M) */
#define KW    256            /* 2*CIN cos/sin (GEMM K) */
#define NW    256            /* couts, f32x2-packed (GEMM N) */
#define NXI   16             /* 4x4 Winograd positions */

#define BM 64
#define BN 64
#define BK 32
#define NKT (KW/BK)          /* 8 */
#define GTH 128

#define AS_STG (BK*BM)                      /* floats per A stage: 2048 (8KB) */
#define BS_STG (BK*BN)                      /* u64 per B stage: 2048 (16KB) */
#define SMEM_DYN (2*(AS_STG*4 + BS_STG*8))  /* 49152 B -> 4 CTAs/SM */

typedef unsigned long long u64;

/* device scratch (zero-init) */
static __device__ float2 g_cs[(size_t)B_ * CIN * HWHW];        /*  51 MB */
static __device__ float  g_V[(size_t)NXI * KW * MW];           /* 205 MB */
static __device__ u64    g_U[(size_t)NXI * KW * NW];           /* 8.4 MB */
static __device__ u64    g_M[(size_t)NXI * NW * MW];           /* 411 MB */

__device__ __forceinline__ void fma2(u64& acc, u64 a, u64 b) {
    asm("fma.rn.f32x2 %0, %1, %2, %0;" : "+l"(acc) : "l"(a), "l"(b));
}
__device__ __forceinline__ u64 add2(u64 a, u64 b) {
    u64 r; asm("add.rn.f32x2 %0, %1, %2;" : "=l"(r) : "l"(a), "l"(b)); return r;
}
__device__ __forceinline__ u64 sub2(u64 a, u64 b) {
    u64 r; asm("sub.rn.f32x2 %0, %1, %2;" : "=l"(r) : "l"(a), "l"(b)); return r;
}
__device__ __forceinline__ u64 bcast2(float v) {
    u64 r; asm("mov.b64 %0, {%1, %1};" : "=l"(r) : "f"(v)); return r;
}
__device__ __forceinline__ u64 pack2(float lo, float hi) {
    u64 r; asm("mov.b64 %0, {%1, %2};" : "=l"(r) : "f"(lo), "f"(hi)); return r;
}
__device__ __forceinline__ void unpack2(u64 v, float& lo, float& hi) {
    asm("mov.b64 {%0, %1}, %2;" : "=f"(lo), "=f"(hi) : "l"(v));
}
__device__ __forceinline__ void cpa16(void* dst, const void* src) {
    unsigned d = (unsigned)__cvta_generic_to_shared(dst);
    asm volatile("cp.async.cg.shared.global [%0], [%1], 16;" :: "r"(d), "l"(src) : "memory");
}

/* ---------- prep: sincos of x ---------- */
__global__ void prep_input_kernel(const float* __restrict__ x) {
    int idx = blockIdx.x * blockDim.x + threadIdx.x;
    if (idx >= B_ * CIN * HWHW) return;
    float s, c;
    sincosf(x[idx], &s, &c);
    g_cs[idx] = make_float2(c, s);
}

/* ---------- F(2,3) weight transform: U = G g G^T, packed (re,im) ---------- */
__global__ void wino_wprep(const float* __restrict__ probe,
                           const float* __restrict__ oang) {
    int idx = blockIdx.x * blockDim.x + threadIdx.x;   /* 256*256 */
    int co = idx & 255;
    int c  = idx >> 8;             /* cin2: 2*ci + s */
    int ci = c >> 1, s = c & 1;
    float gre[3][3], gim[3][3];
#pragma unroll
    for (int tap = 0; tap < 9; tap++) {
        int pidx = ci * 2304 + co * 9 + tap;
        float p = probe[pidx], o = oang[pidx];
        float sp, cp, so, c_o;
        sincosf(p, &sp, &cp);
        sincosf(o, &so, &c_o);
        float a = s ? sp : cp;
        gre[tap / 3][tap % 3] = a * c_o;
        gim[tap / 3][tap % 3] = a * so;
    }
    float Ur[4][4], Ui[4][4];
    {
        float t[4][3];
#pragma unroll
        for (int j = 0; j < 3; j++) {
            t[0][j] = gre[0][j];
            t[1][j] = 0.5f * (gre[0][j] + gre[1][j] + gre[2][j]);
            t[2][j] = 0.5f * (gre[0][j] - gre[1][j] + gre[2][j]);
            t[3][j] = gre[2][j];
        }
#pragma unroll
        for (int i = 0; i < 4; i++) {
            Ur[i][0] = t[i][0];
            Ur[i][1] = 0.5f * (t[i][0] + t[i][1] + t[i][2]);
            Ur[i][2] = 0.5f * (t[i][0] - t[i][1] + t[i][2]);
            Ur[i][3] = t[i][2];
        }
    }
    {
        float t[4][3];
#pragma unroll
        for (int j = 0; j < 3; j++) {
            t[0][j] = gim[0][j];
            t[1][j] = 0.5f * (gim[0][j] + gim[1][j] + gim[2][j]);
            t[2][j] = 0.5f * (gim[0][j] - gim[1][j] + gim[2][j]);
            t[3][j] = gim[2][j];
        }
#pragma unroll
        for (int i = 0; i < 4; i++) {
            Ui[i][0] = t[i][0];
            Ui[i][1] = 0.5f * (t[i][0] + t[i][1] + t[i][2]);
            Ui[i][2] = 0.5f * (t[i][0] - t[i][1] + t[i][2]);
            Ui[i][3] = t[i][2];
        }
    }
#pragma unroll
    for (int i = 0; i < 4; i++)
#pragma unroll
        for (int j = 0; j < 4; j++)
            g_U[(size_t)(i * 4 + j) * KW * NW + (size_t)c * NW + co] =
                pack2(Ur[i][j], Ui[i][j]);
}

/* ---------- F(2,3) input transform: V = B^T d B ---------- */
__global__ void wino_vprep() {
    int m  = blockIdx.x * 256 + threadIdx.x;   /* grid.x = 49 */
    int ci = blockIdx.y;                       /* 0..127 */
    int b  = m / TILES;
    int t  = m - b * TILES;
    int ty = t / 28, tx = t - (t / 28) * 28;
    const float2* plane = g_cs + ((size_t)b * CIN + ci) * HWHW;
    float dc[4][4], ds[4][4];
#pragma unroll
    for (int i = 0; i < 4; i++) {
        int r = 2 * ty - 1 + i;
#pragma unroll
        for (int j = 0; j < 4; j++) {
            int cc = 2 * tx - 1 + j;
            float2 v = make_float2(0.f, 0.f);
            if ((unsigned)r < HW && (unsigned)cc < HW) v = plane[r * HW + cc];
            dc[i][j] = v.x; ds[i][j] = v.y;
        }
    }
    float Vc[4][4], Vs[4][4];
    {
        float tt[4][4];
#pragma unroll
        for (int j = 0; j < 4; j++) {
            tt[0][j] = dc[0][j] - dc[2][j];
            tt[1][j] = dc[1][j] + dc[2][j];
            tt[2][j] = dc[2][j] - dc[1][j];
            tt[3][j] = dc[1][j] - dc[3][j];
        }
#pragma unroll
        for (int i = 0; i < 4; i++) {
            Vc[i][0] = tt[i][0] - tt[i][2];
            Vc[i][1] = tt[i][1] + tt[i][2];
            Vc[i][2] = tt[i][2] - tt[i][1];
            Vc[i][3] = tt[i][1] - tt[i][3];
        }
    }
    {
        float tt[4][4];
#pragma unroll
        for (int j = 0; j < 4; j++) {
            tt[0][j] = ds[0][j] - ds[2][j];
            tt[1][j] = ds[1][j] + ds[2][j];
            tt[2][j] = ds[2][j] - ds[1][j];
            tt[3][j] = ds[1][j] - ds[3][j];
        }
#pragma unroll
        for (int i = 0; i < 4; i++) {
            Vs[i][0] = tt[i][0] - tt[i][2];
            Vs[i][1] = tt[i][1] + tt[i][2];
            Vs[i][2] = tt[i][2] - tt[i][1];
            Vs[i][3] = tt[i][1] - tt[i][3];
        }
    }
#pragma unroll
    for (int i = 0; i < 4; i++)
#pragma unroll
        for (int j = 0; j < 4; j++) {
            float* base = g_V + (size_t)(i * 4 + j) * KW * MW;
            base[(size_t)(2 * ci)     * MW + m] = Vc[i][j];
            base[(size_t)(2 * ci + 1) * MW + m] = Vs[i][j];
        }
}

/* ---------- batched GEMM: M_xi = V_xi^T x U_xi, 4m x 8n f32x2 ---------- */
__global__ __launch_bounds__(GTH) void wino_gemm() {
    extern __shared__ __align__(16) char smraw[];
    float* As = (float*)smraw;                     /* [2][BK][BM] */
    u64*   Bs = (u64*)(smraw + 2 * AS_STG * 4);    /* [2][BK][BN] */
    const int tid = threadIdx.x;
    const int mb = blockIdx.x * BM;
    const int nb = blockIdx.y * BN;
    const int xi = blockIdx.z;
    const float* Ap = g_V + (size_t)xi * KW * MW;
    const u64*   Bp = g_U + (size_t)xi * KW * NW;
    const int m0 = (tid & 15) * 4;
    const int n0 = (tid >> 4) * 8;

    u64 acc[4][8];
#pragma unroll
    for (int i = 0; i < 4; i++)
#pragma unroll
        for (int j = 0; j < 8; j++) acc[i][j] = 0ULL;

    auto load_stage = [&](int kt, int s) {
#pragma unroll
        for (int u = 0; u < 4; u++) {            /* A: 512 x 16B (8KB) */
            int ch = u * GTH + tid;
            int r = ch >> 4, col = (ch & 15) * 4;
            cpa16(As + s * AS_STG + r * BM + col,
                  Ap + (size_t)(kt * BK + r) * MW + mb + col);
        }
#pragma unroll
        for (int u = 0; u < 8; u++) {            /* B: 1024 x 16B (16KB) */
            int ch = u * GTH + tid;
            int r = ch >> 5, col = (ch & 31) * 2;
            cpa16(Bs + s * BS_STG + r * BN + col,
                  Bp + (size_t)(kt * BK + r) * NW + nb + col);
        }
    };

    load_stage(0, 0);
    asm volatile("cp.async.commit_group;" ::: "memory");

#pragma unroll 1
    for (int kt = 0; kt < NKT; kt++) {
        asm volatile("cp.async.wait_group 0;" ::: "memory");
        __syncthreads();
        if (kt + 1 < NKT) {
            load_stage(kt + 1, (kt + 1) & 1);
            asm volatile("cp.async.commit_group;" ::: "memory");
        }
        const int s = kt & 1;
        const float* Ab = As + s * AS_STG + m0;
        const u64*   Bb = Bs + s * BS_STG + n0;
#pragma unroll
        for (int kk = 0; kk < BK; kk++) {
            float4 a = *(const float4*)&Ab[kk * BM];
            u64 b[8];
#pragma unroll
            for (int q = 0; q < 4; q++)
                *(float4*)&b[q * 2] = *(const float4*)&Bb[kk * BN + q * 2];
            u64 av;
            av = bcast2(a.x);
#pragma unroll
            for (int j = 0; j < 8; j++) fma2(acc[0][j], av, b[j]);
            av = bcast2(a.y);
#pragma unroll
            for (int j = 0; j < 8; j++) fma2(acc[1][j], av, b[j]);
            av = bcast2(a.z);
#pragma unroll
            for (int j = 0; j < 8; j++) fma2(acc[2][j], av, b[j]);
            av = bcast2(a.w);
#pragma unroll
            for (int j = 0; j < 8; j++) fma2(acc[3][j], av, b[j]);
        }
    }

    u64* Mp = g_M + (size_t)xi * NW * MW;
#pragma unroll
    for (int j = 0; j < 8; j++) {
        u64* row = Mp + (size_t)(nb + n0 + j) * MW + mb + m0;
#pragma unroll
        for (int i = 0; i < 4; i++) row[i] = acc[i][j];
    }
}

/* ---------- output transform: Y = A^T M A (packed), atan2, store ---------- */
__global__ void wino_out(float* __restrict__ out) {
    int m = blockIdx.x * 256 + threadIdx.x;    /* grid.x = 49 */
    int n = blockIdx.y;                        /* cout 0..255 */
    u64 Mv[4][4];
#pragma unroll
    for (int i = 0; i < 4; i++)
#pragma unroll
        for (int j = 0; j < 4; j++)
            Mv[i][j] = g_M[(size_t)(i * 4 + j) * NW * MW + (size_t)n * MW + m];

    u64 t0[4], t1[4];
#pragma unroll
    for (int j = 0; j < 4; j++) {
        t0[j] = add2(add2(Mv[0][j], Mv[1][j]), Mv[2][j]);
        t1[j] = sub2(sub2(Mv[1][j], Mv[2][j]), Mv[3][j]);
    }
    u64 y00 = add2(add2(t0[0], t0[1]), t0[2]);
    u64 y01 = sub2(sub2(t0[1], t0[2]), t0[3]);
    u64 y10 = add2(add2(t1[0], t1[1]), t1[2]);
    u64 y11 = sub2(sub2(t1[1], t1[2]), t1[3]);

    int b  = m / TILES;
    int t  = m - b * TILES;
    int ty = t / 28, tx = t - (t / 28) * 28;
    float* ob = out + ((size_t)b * COUT + n) * HWHW + (2 * ty) * HW + 2 * tx;
    float re, im;
    unpack2(y00, re, im); ob[0]      = atan2f(im, re);
    unpack2(y01, re, im); ob[1]      = atan2f(im, re);
    unpack2(y10, re, im); ob[HW]     = atan2f(im, re);
    unpack2(y11, re, im); ob[HW + 1] = atan2f(im, re);
}

/* ---------- launch ---------- */
extern "C" void kernel_launch(void* const* d_in, const int* in_sizes, int n_in,
                              void* d_out, int out_size) {
    const float* x     = (const float*)d_in[0];
    const float* probe = (const float*)d_in[1];
    const float* oang  = (const float*)d_in[2];
    float* out = (float*)d_out;

    cudaFuncSetAttribute(wino_gemm, cudaFuncAttributeMaxDynamicSharedMemorySize, SMEM_DYN);

    prep_input_kernel<<<(B_ * CIN * HWHW + 255) / 256, 256>>>(x);
    wino_wprep<<<(KW * NW) / 256, 256>>>(probe, oang);
    {
        dim3 g(MW / 256, CIN);
        wino_vprep<<<g, 256>>>();
    }
    {
        dim3 g(MW / BM, NW / BN, NXI);         /* (196, 4, 16) */
        wino_gemm<<<g, GTH, SMEM_DYN>>>();
    }
    {
        dim3 g(MW / 256, NW);
        wino_out<<<g, 256>>>(out);
    }
}